// round 13
// baseline (speedup 1.0000x reference)
#include <cuda_runtime.h>

#define B_ 8
#define C_ 32
#define F_ 32
#define Q_ 9
#define H_ 32
#define W_ 32
#define CH 4                     // channels per CTA (8-way split)

#define PROWS 34                 // full image + halo rows (-1..32)
#define PSTR  36
#define PLANEF (PROWS * PSTR)    // 1224 floats

typedef unsigned long long u64;
typedef unsigned int u32;

__device__ __forceinline__ u64 pack2(float lo, float hi) {
    u64 r; asm("mov.b64 %0, {%1, %2};" : "=l"(r) : "f"(lo), "f"(hi)); return r;
}
__device__ __forceinline__ void unpack2(u64 v, float& lo, float& hi) {
    asm("mov.b64 {%0, %1}, %2;" : "=f"(lo), "=f"(hi) : "l"(v));
}
__device__ __forceinline__ u64 fma2(u64 a, u64 b, u64 c) {
    u64 d; asm("fma.rn.f32x2 %0, %1, %2, %3;" : "=l"(d) : "l"(a), "l"(b), "l"(c)); return d;
}
__device__ __forceinline__ u64 mul2(u64 a, u64 b) {
    u64 d; asm("mul.rn.f32x2 %0, %1, %2;" : "=l"(d) : "l"(a), "l"(b)); return d;
}
__device__ __forceinline__ float rcpf(float x) {
    float r; asm("rcp.approx.ftz.f32 %0, %1;" : "=f"(r) : "f"(x)); return r;
}
__device__ __forceinline__ void cp4(u32 dst, const float* src, bool ok) {
    const int sz = ok ? 4 : 0;
    asm volatile("cp.async.ca.shared.global [%0], [%1], 4, %2;"
                 :: "r"(dst), "l"(src), "r"(sz));
}
__device__ __forceinline__ void redadd(float* p, float v) {
    asm volatile("red.global.add.f32 [%0], %1;" :: "l"(p), "f"(v) : "memory");
}

__global__ __launch_bounds__(128) void kaconv_zero(float* __restrict__ out)
{
    const int i = blockIdx.x * 128 + threadIdx.x;
    ((float4*)out)[i] = make_float4(0.f, 0.f, 0.f, 0.f);
}

// smem: cs2 = 9*4*10 u64 = 2880B; planes = 2*1224*4 = 9792B -> ~12.7KB
__global__ __launch_bounds__(128, 9) void kaconv_main(
    const float* __restrict__ x,
    const float* __restrict__ nums,
    const float* __restrict__ denoms,
    float* __restrict__ out)
{
    __shared__ __align__(16) u64   cs2[Q_ * CH * 10];  // {a0..a5,b1..b4} each dup'd {v,v}
    __shared__ __align__(16) float planes[2][PLANEF];

    const int tid = threadIdx.x;
    const int blk = blockIdx.x;
    const int co  = blk & 7;               // channel octant
    const int f   = (blk >> 3) & (F_ - 1);
    const int b   = blk >> 8;
    const int c0  = co * CH;

    // ---- stage duplicated coefficient pairs for (f, c-octant) ----
    for (int e = tid; e < Q_ * CH; e += 128) {
        const int q = e >> 2;
        const int c = e & 3;
        const int g = (f * Q_ + q) * C_ + c0 + c;
        const float2* np2 = (const float2*)(nums + (size_t)g * 6);
        const float2 n0 = __ldg(np2);
        const float2 n1 = __ldg(np2 + 1);
        const float2 n2 = __ldg(np2 + 2);
        const float4 d4 = __ldg((const float4*)(denoms + (size_t)g * 4));
        u64* o = cs2 + e * 10;
        o[0] = pack2(n0.x, n0.x); o[1] = pack2(n0.y, n0.y);
        o[2] = pack2(n1.x, n1.x); o[3] = pack2(n1.y, n1.y);
        o[4] = pack2(n2.x, n2.x); o[5] = pack2(n2.y, n2.y);
        o[6] = pack2(d4.x, d4.x); o[7] = pack2(d4.y, d4.y);
        o[8] = pack2(d4.z, d4.z); o[9] = pack2(d4.w, d4.w);
    }

    const float* xb = x + (size_t)(b * C_ + c0) * (H_ * W_);
    const int lane_r = tid >> 5;           // 0..3
    const int col    = tid & 31;

    const u32 sm_pl0 = (u32)__cvta_generic_to_shared(planes[0]);
    const u32 sm_pl1 = (u32)__cvta_generic_to_shared(planes[1]);

    // async stage of full zero-padded plane: rows -1..32, cols -1..32
    auto stage = [&](int c, int buf) {
        const float* xc = xb + c * (H_ * W_);
        const u32 dbase = buf ? sm_pl1 : sm_pl0;
        const int gc0 = col - 1;
        const bool c0ok = (unsigned)gc0 < W_;
        for (int rr = lane_r; rr < PROWS; rr += 4) {
            const int gr = rr - 1;
            const bool rok = (unsigned)gr < H_;
            const float* src = xc + (rok ? gr * W_ : 0);
            cp4(dbase + (rr * PSTR + col) * 4, src + (c0ok ? gc0 : 0), rok & c0ok);
            if (col < 2)
                cp4(dbase + (rr * PSTR + col + 32) * 4, src + 31, rok && (col == 0));
        }
        asm volatile("cp.async.commit_group;");
    };
    stage(0, 0);

    u64 acc0 = 0ULL, acc1 = 0ULL, acc2 = 0ULL, acc3 = 0ULL;

    for (int c = 0; c < CH; ++c) {
        asm volatile("cp.async.wait_group 0;");
        __syncthreads();
        if (c + 1 < CH) stage(c + 1, (c + 1) & 1);
        const float* pl = planes[c & 1] + col;

        #pragma unroll
        for (int q = 0; q < Q_; ++q) {
            const int dy = q / 3;
            const int dx = q - dy * 3;
            // 5x LDS.128 broadcast of duplicated coefficient pairs (no reg-dup MOVs)
            const ulonglong2* cp = (const ulonglong2*)(cs2 + (q * CH + c) * 10);
            const ulonglong2 p01 = cp[0];   // {a0},{a1}
            const ulonglong2 p23 = cp[1];   // {a2},{a3}
            const ulonglong2 p45 = cp[2];   // {a4},{a5}
            const ulonglong2 d12 = cp[3];   // {b1},{b2}
            const ulonglong2 d34 = cp[4];   // {b3},{b4}

            const float* pw = pl + (lane_r + dy) * PSTR + dx;
            const u64 w0 = pack2(pw[0],           pw[4 * PSTR]);
            const u64 w1 = pack2(pw[8 * PSTR],    pw[12 * PSTR]);
            const u64 w2 = pack2(pw[16 * PSTR],   pw[20 * PSTR]);
            const u64 w3 = pack2(pw[24 * PSTR],   pw[28 * PSTR]);

            #define RATBLOCK(WV, ACC)                                   \
            {                                                           \
                u64 nn = fma2(p45.y, WV, p45.x);                        \
                nn = fma2(nn, WV, p23.y);                               \
                nn = fma2(nn, WV, p23.x);                               \
                nn = fma2(nn, WV, p01.y);                               \
                nn = fma2(nn, WV, p01.x);                               \
                u64 ee = fma2(d34.y, WV, d34.x);                        \
                ee = fma2(ee, WV, d12.y);                               \
                ee = fma2(ee, WV, d12.x);                               \
                ee = mul2(ee, WV);                                      \
                float dl, dh; unpack2(ee, dl, dh);                      \
                const float il = rcpf(1.0f + fabsf(dl));                \
                const float ih = rcpf(1.0f + fabsf(dh));                \
                ACC = fma2(nn, pack2(il, ih), ACC);                     \
            }

            RATBLOCK(w0, acc0)
            RATBLOCK(w1, acc1)
            RATBLOCK(w2, acc2)
            RATBLOCK(w3, acc3)
            #undef RATBLOCK
        }
    }

    float r0, r1, r2, r3, r4, r5, r6, r7;
    unpack2(acc0, r0, r1);
    unpack2(acc1, r2, r3);
    unpack2(acc2, r4, r5);
    unpack2(acc3, r6, r7);
    float* ob = out + ((size_t)(b * F_ + f)) * (H_ * W_);
    redadd(&ob[(lane_r)      * W_ + col], r0);
    redadd(&ob[(lane_r + 4)  * W_ + col], r1);
    redadd(&ob[(lane_r + 8)  * W_ + col], r2);
    redadd(&ob[(lane_r + 12) * W_ + col], r3);
    redadd(&ob[(lane_r + 16) * W_ + col], r4);
    redadd(&ob[(lane_r + 20) * W_ + col], r5);
    redadd(&ob[(lane_r + 24) * W_ + col], r6);
    redadd(&ob[(lane_r + 28) * W_ + col], r7);
}

extern "C" void kernel_launch(void* const* d_in, const int* in_sizes, int n_in,
                              void* d_out, int out_size)
{
    const float* x      = (const float*)d_in[0];
    const float* nums   = (const float*)d_in[1];
    const float* denoms = (const float*)d_in[2];
    float* out          = (float*)d_out;
    (void)in_sizes; (void)n_in; (void)out_size;

    kaconv_zero<<<(B_ * F_ * H_ * W_) / (128 * 4), 128>>>(out);
    kaconv_main<<<B_ * F_ * 8, 128>>>(x, nums, denoms, out);
}

// round 14
// speedup vs baseline: 1.1537x; 1.1537x over previous
#include <cuda_runtime.h>

#define B_ 8
#define C_ 32
#define F_ 32
#define Q_ 9
#define H_ 32
#define W_ 32
#define CH 2                     // channels per CTA (16-way split)

#define PROWS 34                 // full image + halo rows (-1..32)
#define PSTR  36
#define PLANEF (PROWS * PSTR)    // 1224 floats

typedef unsigned long long u64;
typedef unsigned int u32;

__device__ __forceinline__ u64 pack2(float lo, float hi) {
    u64 r; asm("mov.b64 %0, {%1, %2};" : "=l"(r) : "f"(lo), "f"(hi)); return r;
}
__device__ __forceinline__ void unpack2(u64 v, float& lo, float& hi) {
    asm("mov.b64 {%0, %1}, %2;" : "=f"(lo), "=f"(hi) : "l"(v));
}
__device__ __forceinline__ u64 fma2(u64 a, u64 b, u64 c) {
    u64 d; asm("fma.rn.f32x2 %0, %1, %2, %3;" : "=l"(d) : "l"(a), "l"(b), "l"(c)); return d;
}
__device__ __forceinline__ u64 mul2(u64 a, u64 b) {
    u64 d; asm("mul.rn.f32x2 %0, %1, %2;" : "=l"(d) : "l"(a), "l"(b)); return d;
}
__device__ __forceinline__ float rcpf(float x) {
    float r; asm("rcp.approx.ftz.f32 %0, %1;" : "=f"(r) : "f"(x)); return r;
}
__device__ __forceinline__ void cp4(u32 dst, const float* src, bool ok) {
    const int sz = ok ? 4 : 0;
    asm volatile("cp.async.ca.shared.global [%0], [%1], 4, %2;"
                 :: "r"(dst), "l"(src), "r"(sz));
}
__device__ __forceinline__ void redadd(float* p, float v) {
    asm volatile("red.global.add.f32 [%0], %1;" :: "l"(p), "f"(v) : "memory");
}

__global__ __launch_bounds__(128) void kaconv_zero(float* __restrict__ out)
{
    const int i = blockIdx.x * 128 + threadIdx.x;
    ((float4*)out)[i] = make_float4(0.f, 0.f, 0.f, 0.f);
}

// smem: cs = 9*2*12 floats = 864B; planes = 2*1224*4 = 9792B -> ~10.7KB
__global__ __launch_bounds__(128, 10) void kaconv_main(
    const float* __restrict__ x,
    const float* __restrict__ nums,
    const float* __restrict__ denoms,
    float* __restrict__ out)
{
    __shared__ __align__(16) float cs[Q_ * CH * 12];   // [a0..a3|a4 a5 b1 b2|b3 b4 - -]
    __shared__ __align__(16) float planes[2][PLANEF];

    const int tid = threadIdx.x;
    const int blk = blockIdx.x;
    const int cg  = blk & 15;              // channel 16th
    const int f   = (blk >> 4) & (F_ - 1);
    const int b   = blk >> 9;
    const int c0  = cg * CH;

    // ---- stage raw coefficients for (f, c-group) ----
    if (tid < Q_ * CH) {
        const int e = tid;
        const int q = e >> 1;
        const int c = e & 1;
        const int g = (f * Q_ + q) * C_ + c0 + c;
        const float2* np2 = (const float2*)(nums + (size_t)g * 6);
        const float2 n0 = __ldg(np2);
        const float2 n1 = __ldg(np2 + 1);
        const float2 n2 = __ldg(np2 + 2);
        const float4 d4 = __ldg((const float4*)(denoms + (size_t)g * 4));
        float* o = cs + e * 12;
        o[0] = n0.x; o[1] = n0.y; o[2]  = n1.x; o[3]  = n1.y;
        o[4] = n2.x; o[5] = n2.y; o[6]  = d4.x; o[7]  = d4.y;
        o[8] = d4.z; o[9] = d4.w; o[10] = 0.f;  o[11] = 0.f;
    }

    const float* xb = x + (size_t)(b * C_ + c0) * (H_ * W_);
    const int lane_r = tid >> 5;           // 0..3
    const int col    = tid & 31;

    const u32 sm_pl0 = (u32)__cvta_generic_to_shared(planes[0]);
    const u32 sm_pl1 = (u32)__cvta_generic_to_shared(planes[1]);

    // async stage of full zero-padded plane: rows -1..32, cols -1..32
    auto stage = [&](int c, int buf) {
        const float* xc = xb + c * (H_ * W_);
        const u32 dbase = buf ? sm_pl1 : sm_pl0;
        const int gc0 = col - 1;
        const bool c0ok = (unsigned)gc0 < W_;
        for (int rr = lane_r; rr < PROWS; rr += 4) {
            const int gr = rr - 1;
            const bool rok = (unsigned)gr < H_;
            const float* src = xc + (rok ? gr * W_ : 0);
            cp4(dbase + (rr * PSTR + col) * 4, src + (c0ok ? gc0 : 0), rok & c0ok);
            if (col < 2)
                cp4(dbase + (rr * PSTR + col + 32) * 4, src + 31, rok && (col == 0));
        }
        asm volatile("cp.async.commit_group;");
    };
    stage(0, 0);

    u64 acc0 = 0ULL, acc1 = 0ULL, acc2 = 0ULL, acc3 = 0ULL;

    #pragma unroll
    for (int c = 0; c < CH; ++c) {
        asm volatile("cp.async.wait_group 0;");
        __syncthreads();
        if (c + 1 < CH) stage(c + 1, (c + 1) & 1);
        const float* pl = planes[c & 1] + col;

        #pragma unroll
        for (int q = 0; q < Q_; ++q) {
            const int dy = q / 3;
            const int dx = q - dy * 3;
            // 3x LDS.128 broadcast of raw coeffs, duplicate in registers
            const float4* cp = (const float4*)(cs + (q * CH + c) * 12);
            const float4 r0 = cp[0];   // a0 a1 a2 a3
            const float4 r1 = cp[1];   // a4 a5 b1 b2
            const float4 r2 = cp[2];   // b3 b4 -- --
            const u64 a0 = pack2(r0.x, r0.x), a1 = pack2(r0.y, r0.y);
            const u64 a2 = pack2(r0.z, r0.z), a3 = pack2(r0.w, r0.w);
            const u64 a4 = pack2(r1.x, r1.x), a5 = pack2(r1.y, r1.y);
            const u64 b1 = pack2(r1.z, r1.z), b2 = pack2(r1.w, r1.w);
            const u64 b3 = pack2(r2.x, r2.x), b4 = pack2(r2.y, r2.y);

            const float* pw = pl + (lane_r + dy) * PSTR + dx;
            const u64 w0 = pack2(pw[0],           pw[4 * PSTR]);
            const u64 w1 = pack2(pw[8 * PSTR],    pw[12 * PSTR]);
            const u64 w2 = pack2(pw[16 * PSTR],   pw[20 * PSTR]);
            const u64 w3 = pack2(pw[24 * PSTR],   pw[28 * PSTR]);

            #define RATBLOCK(WV, ACC)                                   \
            {                                                           \
                u64 nn = fma2(a5, WV, a4);                              \
                nn = fma2(nn, WV, a3);                                  \
                nn = fma2(nn, WV, a2);                                  \
                nn = fma2(nn, WV, a1);                                  \
                nn = fma2(nn, WV, a0);                                  \
                u64 ee = fma2(b4, WV, b3);                              \
                ee = fma2(ee, WV, b2);                                  \
                ee = fma2(ee, WV, b1);                                  \
                ee = mul2(ee, WV);                                      \
                float dl, dh; unpack2(ee, dl, dh);                      \
                const float il = rcpf(1.0f + fabsf(dl));                \
                const float ih = rcpf(1.0f + fabsf(dh));                \
                ACC = fma2(nn, pack2(il, ih), ACC);                     \
            }

            RATBLOCK(w0, acc0)
            RATBLOCK(w1, acc1)
            RATBLOCK(w2, acc2)
            RATBLOCK(w3, acc3)
            #undef RATBLOCK
        }
    }

    float r0, r1, r2, r3, r4, r5, r6, r7;
    unpack2(acc0, r0, r1);
    unpack2(acc1, r2, r3);
    unpack2(acc2, r4, r5);
    unpack2(acc3, r6, r7);
    float* ob = out + ((size_t)(b * F_ + f)) * (H_ * W_);
    redadd(&ob[(lane_r)      * W_ + col], r0);
    redadd(&ob[(lane_r + 4)  * W_ + col], r1);
    redadd(&ob[(lane_r + 8)  * W_ + col], r2);
    redadd(&ob[(lane_r + 12) * W_ + col], r3);
    redadd(&ob[(lane_r + 16) * W_ + col], r4);
    redadd(&ob[(lane_r + 20) * W_ + col], r5);
    redadd(&ob[(lane_r + 24) * W_ + col], r6);
    redadd(&ob[(lane_r + 28) * W_ + col], r7);
}

extern "C" void kernel_launch(void* const* d_in, const int* in_sizes, int n_in,
                              void* d_out, int out_size)
{
    const float* x      = (const float*)d_in[0];
    const float* nums   = (const float*)d_in[1];
    const float* denoms = (const float*)d_in[2];
    float* out          = (float*)d_out;
    (void)in_sizes; (void)n_in; (void)out_size;

    kaconv_zero<<<(B_ * F_ * H_ * W_) / (128 * 4), 128>>>(out);
    kaconv_main<<<B_ * F_ * 16, 128>>>(x, nums, denoms, out);
}